// round 5
// baseline (speedup 1.0000x reference)
#include <cuda_runtime.h>
#include <cstdint>
#include <cstddef>

// Problem dims (fixed per reference)
#define BB 256
#define TT 512
#define II 64
#define HH 128
#define GG 512   // 4*H

typedef unsigned long long ull;

// Scratch for precomputed input-gate projections: [B, T, 4H] fp32 = 256 MB.
__device__ float g_xg[(size_t)BB * TT * GG];

__device__ __forceinline__ float fsig(float x) {
    return __fdividef(1.f, 1.f + __expf(-x));
}
__device__ __forceinline__ float ftanh(float x) {
    float e = __expf(2.f * x);
    return 1.f - __fdividef(2.f, e + 1.f);
}

// Packed f32x2 ops (sm_103a; ptxas never auto-fuses these)
__device__ __forceinline__ ull fma2(ull a, ull b, ull c) {
    ull d;
    asm("fma.rn.f32x2 %0, %1, %2, %3;" : "=l"(d) : "l"(a), "l"(b), "l"(c));
    return d;
}
__device__ __forceinline__ ull add2(ull a, ull b) {
    ull d;
    asm("add.rn.f32x2 %0, %1, %2;" : "=l"(d) : "l"(a), "l"(b));
    return d;
}
__device__ __forceinline__ ull pack2(float x, float y) {
    ull r;
    asm("mov.b64 %0, {%1, %2};" : "=l"(r) : "f"(x), "f"(y));
    return r;
}
__device__ __forceinline__ float hsum2(ull a) {
    uint2 u = *reinterpret_cast<uint2*>(&a);
    return __uint_as_float(u.x) + __uint_as_float(u.y);
}
__device__ __forceinline__ float lo2(ull a) { return __uint_as_float((unsigned)a); }
__device__ __forceinline__ float hi2(ull a) { return __uint_as_float((unsigned)(a >> 32)); }

// ---------------------------------------------------------------------------
// Kernel 1: x_gates GEMM, f32x2-packed, PERSISTENT blocks.
// M = B*T = 131072, N = 512, K = 64. Each block stages W (132KB) + bias ONCE,
// then loops over M-tiles of 64 rows (2048 tiles / 148 blocks).
// ---------------------------------------------------------------------------
#define NTILES 2048

__global__ __launch_bounds__(512, 1) void xg_gemm(
    const float* __restrict__ X,
    const float* __restrict__ Wih,
    const float* __restrict__ bih,
    const float* __restrict__ bhh)
{
    extern __shared__ __align__(16) float sm[];
    float* Xs = sm;                 // [64][68]  (m-contiguous rows)
    float* Ws = sm + 64 * 68;       // [64][516]
    float* bs = Ws + 64 * 516;      // [512]
    const int tid = threadIdx.x;

    bs[tid] = bih[tid] + bhh[tid];
    for (int idx = tid; idx < 512 * 64; idx += 512) {
        int n = idx >> 6, k = idx & 63;
        Ws[k * 516 + n] = Wih[n * II + k];
    }

    const int ni = tid & 63, mi = tid >> 6;
    const int nb = ni * 8,  mb = mi * 8;

    for (int tile = blockIdx.x; tile < NTILES; tile += gridDim.x) {
        const int m0 = tile * 64;
        __syncthreads();   // previous tile's Xs readers done / Ws staged (1st iter)
        for (int idx = tid; idx < 64 * 64; idx += 512) {
            int m = idx >> 6, k = idx & 63;
            Xs[k * 68 + m] = X[(size_t)(m0 + m) * II + k];
        }
        __syncthreads();

        // acc2[mp][n] : packed {m=2mp, m=2mp+1} for column nb+n
        ull acc2[4][8];
        #pragma unroll
        for (int n = 0; n < 8; n++) {
            float bv = bs[nb + n];
            ull bp = pack2(bv, bv);
            #pragma unroll
            for (int mp = 0; mp < 4; mp++) acc2[mp][n] = bp;
        }

        #pragma unroll 4
        for (int k = 0; k < 64; k++) {
            ulonglong2 a01 = *(const ulonglong2*)&Xs[k * 68 + mb];
            ulonglong2 a23 = *(const ulonglong2*)&Xs[k * 68 + mb + 4];
            ull a[4] = {a01.x, a01.y, a23.x, a23.y};
            float4 b0 = *(const float4*)&Ws[k * 516 + nb];
            float4 b1 = *(const float4*)&Ws[k * 516 + nb + 4];
            float bv[8] = {b0.x, b0.y, b0.z, b0.w, b1.x, b1.y, b1.z, b1.w};
            #pragma unroll
            for (int n = 0; n < 8; n++) {
                ull bb = pack2(bv[n], bv[n]);
                #pragma unroll
                for (int mp = 0; mp < 4; mp++)
                    acc2[mp][n] = fma2(a[mp], bb, acc2[mp][n]);
            }
        }

        #pragma unroll
        for (int mp = 0; mp < 4; mp++) {
            size_t row0 = (size_t)(m0 + mb + 2 * mp);
            float4* o0 = (float4*)&g_xg[row0 * GG + nb];
            float4* o1 = (float4*)&g_xg[(row0 + 1) * GG + nb];
            o0[0] = make_float4(lo2(acc2[mp][0]), lo2(acc2[mp][1]), lo2(acc2[mp][2]), lo2(acc2[mp][3]));
            o0[1] = make_float4(lo2(acc2[mp][4]), lo2(acc2[mp][5]), lo2(acc2[mp][6]), lo2(acc2[mp][7]));
            o1[0] = make_float4(hi2(acc2[mp][0]), hi2(acc2[mp][1]), hi2(acc2[mp][2]), hi2(acc2[mp][3]));
            o1[1] = make_float4(hi2(acc2[mp][4]), hi2(acc2[mp][5]), hi2(acc2[mp][6]), hi2(acc2[mp][7]));
        }
    }
}

// ---------------------------------------------------------------------------
// Kernel 2: LSTM scan. 128 blocks x 512 threads (16 warps) — k-SPLIT layout.
// Lane pair (even, odd) shares gates: thread owns gate-slots gA = tid>>1 and
// gB = gA + 256, covering k-half [khalf*64, khalf*64+64) with khalf = tid&1.
// 40 of the 64 k in registers (20 f32x2 pairs per slot), 24 from smem.
// Partial dots combined across the lane pair with one shfl_xor per total.
// Same crossbar floor as R4 but 2x warps -> hides LDS latency + update tail.
// ---------------------------------------------------------------------------
#define KREG2 40                 // per-slot k-values in registers
#define QS2   6                  // (64-KREG2)/4 smem ulonglong2 loads per slot

__global__ __launch_bounds__(512, 1) void lstm_scan(
    const float* __restrict__ hprev,
    const float* __restrict__ cprev,
    const float* __restrict__ Whh,
    float* __restrict__ out)
{
    extern __shared__ __align__(16) float sm[];
    ulonglong2* wA = (ulonglong2*)sm;            // [QS2][512]
    ulonglong2* wB = wA + QS2 * 512;             // [QS2][512]
    float* h0s = (float*)(wB + QS2 * 512);       // [128]
    float* h1s = h0s + 128;                      // [128]
    float* gsm = h1s + 128;                      // [2][512]

    const int tid   = threadIdx.x;
    const int b0    = blockIdx.x * 2;
    const int gA    = tid >> 1;                  // 0..255
    const int gB    = gA + 256;
    const int koff  = (tid & 1) * 64;            // k-half base

    // Stage smem weight tails (k = koff+KREG2 .. koff+63) for both slots
    #pragma unroll
    for (int q = 0; q < QS2; q++) {
        wA[q * 512 + tid] = *(const ulonglong2*)&Whh[gA * HH + koff + KREG2 + 4 * q];
        wB[q * 512 + tid] = *(const ulonglong2*)&Whh[gB * HH + koff + KREG2 + 4 * q];
    }

    // Register weights: 20 packed pairs per slot
    ull wrA[KREG2 / 2], wrB[KREG2 / 2];
    #pragma unroll
    for (int p = 0; p < KREG2 / 2; p++) {
        wrA[p] = *(const ull*)&Whh[gA * HH + koff + 2 * p];
        wrB[p] = *(const ull*)&Whh[gB * HH + koff + 2 * p];
    }

    // Init h, c : threads 0..255 own (b = tid>>7, j = tid&127)
    const int b = tid >> 7, j = tid & 127;
    float* hs = b ? h1s : h0s;
    float c = 0.f;
    if (tid < 256) {
        hs[j] = hprev[(b0 + b) * HH + j];
        c = cprev[(b0 + b) * HH + j];
    }
    __syncthreads();

    const float* xb0 = g_xg + (size_t)b0 * TT * GG;
    const float* xb1 = xb0 + (size_t)TT * GG;

    // Prefetch t=0 x values (per-thread gates gA, gB; lane pairs duplicate)
    float xA0 = xb0[gA], xB0 = xb0[gB];
    float xA1 = xb1[gA], xB1 = xb1[gB];

    for (int t = 0; t < TT; t++) {
        // Prefetch next step's x (consumed one full GEMV later)
        size_t noff = (size_t)(t + 1 < TT ? t + 1 : t) * GG;
        float nA0 = xb0[noff + gA], nB0 = xb0[noff + gB];
        float nA1 = xb1[noff + gA], nB1 = xb1[noff + gB];

        // 8 accumulator chains: {slot A,B} x {batch 0,1} x {even,odd pair}
        ull aA0x = 0, aA0y = 0, aA1x = 0, aA1y = 0;
        ull aB0x = 0, aB0y = 0, aB1x = 0, aB1y = 0;

        // k = koff .. koff+KREG2-1 : register weights
        #pragma unroll
        for (int q = 0; q < KREG2 / 4; q++) {
            ulonglong2 h0 = *(const ulonglong2*)&h0s[koff + 4 * q];
            ulonglong2 h1 = *(const ulonglong2*)&h1s[koff + 4 * q];
            ull w0 = wrA[2 * q], w1 = wrA[2 * q + 1];
            ull v0 = wrB[2 * q], v1 = wrB[2 * q + 1];
            aA0x = fma2(w0, h0.x, aA0x);  aA0y = fma2(w1, h0.y, aA0y);
            aA1x = fma2(w0, h1.x, aA1x);  aA1y = fma2(w1, h1.y, aA1y);
            aB0x = fma2(v0, h0.x, aB0x);  aB0y = fma2(v1, h0.y, aB0y);
            aB1x = fma2(v0, h1.x, aB1x);  aB1y = fma2(v1, h1.y, aB1y);
        }
        // k = koff+KREG2 .. koff+63 : smem weights
        #pragma unroll
        for (int q = 0; q < QS2; q++) {
            ulonglong2 h0 = *(const ulonglong2*)&h0s[koff + KREG2 + 4 * q];
            ulonglong2 h1 = *(const ulonglong2*)&h1s[koff + KREG2 + 4 * q];
            ulonglong2 wa = wA[q * 512 + tid];
            ulonglong2 wb = wB[q * 512 + tid];
            aA0x = fma2(wa.x, h0.x, aA0x);  aA0y = fma2(wa.y, h0.y, aA0y);
            aA1x = fma2(wa.x, h1.x, aA1x);  aA1y = fma2(wa.y, h1.y, aA1y);
            aB0x = fma2(wb.x, h0.x, aB0x);  aB0y = fma2(wb.y, h0.y, aB0y);
            aB1x = fma2(wb.x, h1.x, aB1x);  aB1y = fma2(wb.y, h1.y, aB1y);
        }

        // Combine lane-pair partials (khalf 0 + khalf 1)
        float sA0 = hsum2(add2(aA0x, aA0y));
        float sB0 = hsum2(add2(aB0x, aB0y));
        float sA1 = hsum2(add2(aA1x, aA1y));
        float sB1 = hsum2(add2(aB1x, aB1y));
        sA0 += __shfl_xor_sync(0xFFFFFFFFu, sA0, 1);
        sB0 += __shfl_xor_sync(0xFFFFFFFFu, sB0, 1);
        sA1 += __shfl_xor_sync(0xFFFFFFFFu, sA1, 1);
        sB1 += __shfl_xor_sync(0xFFFFFFFFu, sB1, 1);

        if ((tid & 1) == 0) {
            gsm[gA]       = xA0 + sA0;
            gsm[gB]       = xB0 + sB0;
            gsm[512 + gA] = xA1 + sA1;
            gsm[512 + gB] = xB1 + sB1;
        }
        __syncthreads();

        // Cell update: threads 0..255, one (batch, cell) each
        if (tid < 256) {
            const float* gb = gsm + b * 512;
            float ig = fsig(gb[j]);             // PyTorch order: i, f, g, o
            float fg = fsig(gb[j + 128]);
            float gg = ftanh(gb[j + 256]);
            float og = fsig(gb[j + 384]);
            c = fg * c + ig * gg;
            float h = og * ftanh(c);
            hs[j] = h;
            out[((size_t)(b0 + b) * TT + t) * HH + j] = h;
        }
        __syncthreads();

        xA0 = nA0; xB0 = nB0; xA1 = nA1; xB1 = nB1;
    }

    // h_last, c_last appended after outputs
    if (tid < 256) {
        size_t base = (size_t)BB * TT * HH;
        out[base + (b0 + b) * HH + j] = hs[j];
        out[base + (size_t)BB * HH + (b0 + b) * HH + j] = c;
    }
}

// ---------------------------------------------------------------------------
extern "C" void kernel_launch(void* const* d_in, const int* in_sizes, int n_in,
                              void* d_out, int out_size)
{
    const float* inputs = (const float*)d_in[0];
    const float* hprev  = (const float*)d_in[1];
    const float* cprev  = (const float*)d_in[2];
    const float* Wih    = (const float*)d_in[3];
    const float* Whh    = (const float*)d_in[4];
    const float* bih    = (const float*)d_in[5];
    const float* bhh    = (const float*)d_in[6];
    float* out = (float*)d_out;
    (void)in_sizes; (void)n_in; (void)out_size;

    const size_t smem1 = (size_t)(64 * 68 + 64 * 516 + 512) * sizeof(float);     // ~148 KB
    const size_t smem2 = (size_t)(2 * QS2 * 512) * sizeof(ulonglong2)
                       + (size_t)(256 + 1024) * sizeof(float);                   // ~101 KB
    cudaFuncSetAttribute(xg_gemm,   cudaFuncAttributeMaxDynamicSharedMemorySize, (int)smem1);
    cudaFuncSetAttribute(lstm_scan, cudaFuncAttributeMaxDynamicSharedMemorySize, (int)smem2);

    xg_gemm  <<<148, 512, smem1>>>(inputs, Wih, bih, bhh);
    lstm_scan<<<128, 512, smem2>>>(hprev, cprev, Whh, out);
}